// round 17
// baseline (speedup 1.0000x reference)
#include <cuda_runtime.h>
#include <math.h>

#define W_ 256
#define H_ 256
#define NMAX 768
#define NWORDS 24               // ceil(768/32)
#define CUT_SIGMA 5.5412636f    // log(255): alpha >= 1/255  <=>  sigma <= log(255)

// depth-sorted gaussian data (written at rank)
__device__ float4 g_A[NMAX];    // mx, my, 0.5*conicA, 0.5*conicC
__device__ float4 g_B[NMAX];    // conicB, bias(=-log op), r, g
__device__ float  g_bv[NMAX];   // blue
__device__ float2 g_K[NMAX];    // ku = -cB/cA, kv = -cB/cC (edge-minimizer slopes)

// Fused preprocess + stable rank sort. ONE WARP PER GAUSSIAN; z staged in smem.
__global__ __launch_bounds__(256) void gs_prep_sort(
        const float* __restrict__ means,
        const float* __restrict__ quats,
        const float* __restrict__ scales,
        const float* __restrict__ opac_in,
        const float* __restrict__ rgbs,
        int n) {
    __shared__ float s_z[NMAX];
    const int tid = threadIdx.x;
    const int gw = (blockIdx.x * 256 + tid) >> 5;
    const int lane = tid & 31;

    for (int j = tid; j < n; j += 256)
        s_z[j] = __ldg(&means[j*3+2]);
    __syncthreads();

    if (gw >= n) return;

    float zi = s_z[gw];
    int rank = 0;
    for (int j = lane; j < n; j += 32) {
        float zj = s_z[j];
        rank += (zj < zi || (zj == zi && j < gw)) ? 1 : 0;
    }
    #pragma unroll
    for (int o = 16; o > 0; o >>= 1)
        rank += __shfl_down_sync(0xffffffffu, rank, o);

    if (lane != 0) return;

    const int i = gw;
    float qw = __ldg(&quats[i*4+0]), qx = __ldg(&quats[i*4+1]);
    float qy = __ldg(&quats[i*4+2]), qz = __ldg(&quats[i*4+3]);
    float sx = __ldg(&scales[i*3+0]), sy = __ldg(&scales[i*3+1]), szc = __ldg(&scales[i*3+2]);
    float tx = __ldg(&means[i*3+0]), ty = __ldg(&means[i*3+1]);
    float opraw = __ldg(&opac_in[i]);
    float rr = __ldg(&rgbs[i*3+0]), rg = __ldg(&rgbs[i*3+1]), rb = __ldg(&rgbs[i*3+2]);

    float inv = rsqrtf(qw*qw + qx*qx + qy*qy + qz*qz);
    float w = qw*inv, x = qx*inv, y = qy*inv, z = qz*inv;

    float R00 = 1.f - 2.f*(y*y + z*z), R01 = 2.f*(x*y - w*z), R02 = 2.f*(x*z + w*y);
    float R10 = 2.f*(x*y + w*z), R11 = 1.f - 2.f*(x*x + z*z), R12 = 2.f*(y*z - w*x);
    float R20 = 2.f*(x*z - w*y), R21 = 2.f*(y*z + w*x), R22 = 1.f - 2.f*(x*x + y*y);

    float s0 = sx*sx, s1 = sy*sy, s2 = szc*szc;

    float C00 = R00*R00*s0 + R01*R01*s1 + R02*R02*s2;
    float C01 = R00*R10*s0 + R01*R11*s1 + R02*R12*s2;
    float C02 = R00*R20*s0 + R01*R21*s1 + R02*R22*s2;
    float C11 = R10*R10*s0 + R11*R11*s1 + R12*R12*s2;
    float C12 = R10*R20*s0 + R11*R21*s1 + R12*R22*s2;
    float C22 = R20*R20*s0 + R21*R21*s1 + R22*R22*s2;

    float tz = zi + 8.0f;
    const float f = 128.0f;
    float iz = 1.0f / tz;
    float j00 = f * iz;
    float j02 = -f * tx * iz * iz;
    float j12 = -f * ty * iz * iz;

    float a = j00*j00*C00 + 2.f*j00*j02*C02 + j02*j02*C22 + 0.3f;
    float b = j00*j00*C01 + j00*j12*C02 + j02*j00*C12 + j02*j12*C22;
    float c = j00*j00*C11 + 2.f*j00*j12*C12 + j12*j12*C22 + 0.3f;

    float det = a*c - b*b;
    float idet = 1.0f / det;
    float cA = c * idet, cB = -b * idet, cC = a * idet;

    float mx = f * tx * iz + 128.0f;
    float my = f * ty * iz + 128.0f;

    float op = 1.0f / (1.0f + __expf(-opraw));
    float cr = 1.0f / (1.0f + __expf(-rr));
    float cg = 1.0f / (1.0f + __expf(-rg));
    float cb = 1.0f / (1.0f + __expf(-rb));

    float bias = -__logf(op);

    g_A[rank]  = make_float4(mx, my, 0.5f * cA, 0.5f * cC);
    g_B[rank]  = make_float4(cB, bias, cr, cg);
    g_bv[rank] = cb;
    // edge-minimizer slopes: on edge u fixed, v* = -cB*u/cC = kv*u; etc.
    g_K[rank]  = make_float2(-cB / cA, -cB / cC);
}

// Exact tile-ellipse hit test: min over rect [tlx,thx]x[tly,thy] of
// za*u^2 + zc*v^2 + cb*u*v + bias  (u = px - mx, v = py - my).
// PD quadratic on a box: min at interior (0,0) or clamped edge minimizer.
__device__ __forceinline__ bool tile_hit(
        float4 A, float cb, float bias, float ku, float kv,
        float tlx, float thx, float tly, float thy) {
    float za = A.z, zc = A.w;
    float ux0 = tlx - A.x, ux1 = thx - A.x;
    float vy0 = tly - A.y, vy1 = thy - A.y;
    bool inside = (ux0 <= 0.f) & (ux1 >= 0.f) & (vy0 <= 0.f) & (vy1 >= 0.f);
    // edges u = ux0, ux1 (1D min over v, clamped)
    float v0 = fminf(fmaxf(kv * ux0, vy0), vy1);
    float v1 = fminf(fmaxf(kv * ux1, vy0), vy1);
    float e0 = fmaf(za, ux0*ux0, fmaf(zc, v0*v0, cb*ux0*v0));
    float e1 = fmaf(za, ux1*ux1, fmaf(zc, v1*v1, cb*ux1*v1));
    // edges v = vy0, vy1
    float u0 = fminf(fmaxf(ku * vy0, ux0), ux1);
    float u1 = fminf(fmaxf(ku * vy1, ux0), ux1);
    float e2 = fmaf(za, u0*u0, fmaf(zc, vy0*vy0, cb*u0*vy0));
    float e3 = fmaf(za, u1*u1, fmaf(zc, vy1*vy1, cb*u1*vy1));
    float m = fminf(fminf(e0, e1), fminf(e2, e3));
    m = inside ? 0.f : m;
    return (m + bias) <= (CUT_SIGMA + 1e-4f);   // margin: false-keep only
}

// 8x8 tile per block, 256 threads. Exact-ellipse ballot binning, parallel
// expand+stage, 8-way split (32-thread segments, 2 px/thread same column).
__global__ __launch_bounds__(256) void gs_render(float* __restrict__ out, int n) {
    __shared__ float4 sA[NMAX + 1];
    __shared__ float4 sB[NMAX + 1];
    __shared__ float  sBV[NMAX + 1];
    __shared__ unsigned s_mask[NWORDS];
    __shared__ float cT[7][64], cR[7][64], cG[7][64], cBv[7][64];

    const int tid = threadIdx.x;
    const int warp = tid >> 5, lane = tid & 31;
    const int px0 = blockIdx.x * 8, py0 = blockIdx.y * 8;

    const float tlx = px0 + 0.5f, thx = px0 + 7.5f;
    const float tly = py0 + 0.5f, thy = py0 + 7.5f;

    // ballot binning with exact ellipse test: warp w covers words 3w..3w+2.
    // Issue all loads first (MLP), then the tests + ballots.
    int g0 = (warp * 3 + 0) * 32 + lane;
    int g1 = (warp * 3 + 1) * 32 + lane;
    int g2 = (warp * 3 + 2) * 32 + lane;
    bool in0 = g0 < n, in1 = g1 < n, in2 = g2 < n;
    float4 A0 = in0 ? __ldg(&g_A[g0]) : make_float4(0.f, 0.f, 0.f, 0.f);
    float4 A1 = in1 ? __ldg(&g_A[g1]) : make_float4(0.f, 0.f, 0.f, 0.f);
    float4 A2 = in2 ? __ldg(&g_A[g2]) : make_float4(0.f, 0.f, 0.f, 0.f);
    float4 B0 = in0 ? __ldg(&g_B[g0]) : make_float4(0.f, 1e30f, 0.f, 0.f);
    float4 B1 = in1 ? __ldg(&g_B[g1]) : make_float4(0.f, 1e30f, 0.f, 0.f);
    float4 B2 = in2 ? __ldg(&g_B[g2]) : make_float4(0.f, 1e30f, 0.f, 0.f);
    float2 K0 = in0 ? __ldg(&g_K[g0]) : make_float2(0.f, 0.f);
    float2 K1 = in1 ? __ldg(&g_K[g1]) : make_float2(0.f, 0.f);
    float2 K2 = in2 ? __ldg(&g_K[g2]) : make_float2(0.f, 0.f);

    bool mypred[3];
    unsigned myms[3];
    mypred[0] = tile_hit(A0, B0.x, B0.y, K0.x, K0.y, tlx, thx, tly, thy);
    mypred[1] = tile_hit(A1, B1.x, B1.y, K1.x, K1.y, tlx, thx, tly, thy);
    mypred[2] = tile_hit(A2, B2.x, B2.y, K2.x, K2.y, tlx, thx, tly, thy);
    myms[0] = __ballot_sync(0xffffffffu, mypred[0]);
    myms[1] = __ballot_sync(0xffffffffu, mypred[1]);
    myms[2] = __ballot_sync(0xffffffffu, mypred[2]);
    if (lane < 3) s_mask[warp * 3 + lane] =
        (lane == 0) ? myms[0] : (lane == 1) ? myms[1] : myms[2];
    __syncthreads();

    // redundant per-warp 24-word popc prefix
    unsigned wm = (lane < NWORDS) ? s_mask[lane] : 0u;
    int pc = __popc(wm);
    int sc = pc;
    #pragma unroll
    for (int o = 1; o < 32; o <<= 1) {
        int v = __shfl_up_sync(0xffffffffu, sc, o);
        if (lane >= o) sc += v;
    }
    const int cnt = __shfl_sync(0xffffffffu, sc, NWORDS - 1);
    const int excl = sc - pc;

    // fused expand + stage (A/B already in registers; only bv needs a load)
    {
        unsigned m = myms[0];
        int base = __shfl_sync(0xffffffffu, excl, warp * 3 + 0);
        if (mypred[0]) {
            int pos = base + __popc(m & ((1u << lane) - 1u));
            sA[pos] = A0; sB[pos] = B0; sBV[pos] = __ldg(&g_bv[g0]);
        }
        m = myms[1];
        base = __shfl_sync(0xffffffffu, excl, warp * 3 + 1);
        if (mypred[1]) {
            int pos = base + __popc(m & ((1u << lane) - 1u));
            sA[pos] = A1; sB[pos] = B1; sBV[pos] = __ldg(&g_bv[g1]);
        }
        m = myms[2];
        base = __shfl_sync(0xffffffffu, excl, warp * 3 + 2);
        if (mypred[2]) {
            int pos = base + __popc(m & ((1u << lane) - 1u));
            sA[pos] = A2; sB[pos] = B2; sBV[pos] = __ldg(&g_bv[g2]);
        }
    }
    __syncthreads();

    const int seg = tid >> 5;      // 0..7: eighth of the sorted list (1 warp)
    const int x0 = lane & 7;       // column
    const int y0 = lane >> 3;      // rows y0 and y0+4
    const int kb = (seg * cnt) >> 3;
    const int ke = ((seg + 1) * cnt) >> 3;

    const float pxc  = px0 + x0 + 0.5f;
    const float pyc0 = py0 + y0 + 0.5f;
    const float pyc1 = pyc0 + 4.0f;

    float T0 = 1.0f, r0 = 0.0f, g0f = 0.0f, b0f = 0.0f;
    float T1 = 1.0f, r1 = 0.0f, g1f = 0.0f, b1f = 0.0f;

    float4 A = sA[kb];
    float4 B = sB[kb];
    float  bv = sBV[kb];
    for (int k = kb; k < ke; k++) {
        float4 An = sA[k + 1];
        float4 Bn = sB[k + 1];
        float  bvn = sBV[k + 1];
        float dx    = pxc - A.x;
        float base  = fmaf(A.z, dx*dx, B.y);   // 0.5cA*dx^2 + bias
        float cbdx  = B.x * dx;                // cB*dx
        float dy0 = pyc0 - A.y;
        float dy1 = pyc1 - A.y;
        float sg0 = fmaf(A.w, dy0*dy0, fmaf(cbdx, dy0, base));
        float sg1 = fmaf(A.w, dy1*dy1, fmaf(cbdx, dy1, base));
        if (fminf(sg0, sg1) <= CUT_SIGMA) {
            if (sg0 <= CUT_SIGMA) {
                float al = __expf(-sg0);       // <= op < ALPHA_MAX always
                float wt = T0 * al;
                r0  = fmaf(wt, B.z, r0);
                g0f = fmaf(wt, B.w, g0f);
                b0f = fmaf(wt, bv, b0f);
                T0 -= wt;
            }
            if (sg1 <= CUT_SIGMA) {
                float al = __expf(-sg1);
                float wt = T1 * al;
                r1  = fmaf(wt, B.z, r1);
                g1f = fmaf(wt, B.w, g1f);
                b1f = fmaf(wt, bv, b1f);
                T1 -= wt;
            }
            if (T0 < 2e-6f && T1 < 2e-6f) break;  // truncation < 2e-6 absolute
        }
        A = An; B = Bn; bv = bvn;
    }

    const int p0 = (y0 << 3) + x0;
    if (seg > 0) {
        cT[seg-1][p0]      = T0;  cT[seg-1][p0+32]  = T1;
        cR[seg-1][p0]      = r0;  cR[seg-1][p0+32]  = r1;
        cG[seg-1][p0]      = g0f; cG[seg-1][p0+32]  = g1f;
        cBv[seg-1][p0]     = b0f; cBv[seg-1][p0+32] = b1f;
    }
    __syncthreads();

    if (seg == 0) {
        #pragma unroll
        for (int h = 0; h < 2; h++) {
            int p = p0 + h * 32;
            float Tf = h ? T1 : T0;
            float r  = h ? r1 : r0, g = h ? g1f : g0f, b = h ? b1f : b0f;
            float rr = cR[6][p], gg = cG[6][p], bb = cBv[6][p];
            #pragma unroll
            for (int s = 5; s >= 0; s--) {
                float Ts = cT[s][p];
                rr = fmaf(Ts, rr, cR[s][p]);
                gg = fmaf(Ts, gg, cG[s][p]);
                bb = fmaf(Ts, bb, cBv[s][p]);
            }
            rr = fmaf(Tf, rr, r);
            gg = fmaf(Tf, gg, g);
            bb = fmaf(Tf, bb, b);
            int po = (py0 + y0 + h * 4) * W_ + (px0 + x0);
            out[3*po + 0] = rr;
            out[3*po + 1] = gg;
            out[3*po + 2] = bb;
        }
    }
}

extern "C" void kernel_launch(void* const* d_in, const int* in_sizes, int n_in,
                              void* d_out, int out_size) {
    const float* means  = (const float*)d_in[1];
    const float* quats  = (const float*)d_in[2];
    const float* scales = (const float*)d_in[3];
    const float* opac   = (const float*)d_in[4];
    const float* rgbs   = (const float*)d_in[5];
    int n = in_sizes[4];
    if (n > NMAX) n = NMAX;

    gs_prep_sort<<<(n * 32 + 255) / 256, 256>>>(means, quats, scales, opac, rgbs, n);
    dim3 grid(W_ / 8, H_ / 8), block(256);
    gs_render<<<grid, block>>>((float*)d_out, n);
}